// round 4
// baseline (speedup 1.0000x reference)
#include <cuda_runtime.h>
#include <cstdint>

// Problem constants
#define NUM_HEADS 10
#define DICT      20
#define NJ        200            // NUM_HEADS * DICT
#define BATCH_N   262144

// out[b, j] = relu( x[b,:] . (gamma*W3[j,:] + W4[j,:]) )
// (softmax over a size-1 axis == 1, so the attention block is the identity on v;
//  W1, W2 are dead.)

__device__ float g_weff[NJ * DICT];   // effective weight, row-major [j][d]

__global__ void prep_weff_kernel(const float* __restrict__ W3,
                                 const float* __restrict__ W4,
                                 const float* __restrict__ gamma) {
    int i = blockIdx.x * blockDim.x + threadIdx.x;
    if (i < NJ * DICT) {
        g_weff[i] = gamma[0] * W3[i] + W4[i];
    }
}

// Packed f32x2 FMA (Blackwell): d = a*b + c on two fp32 lanes in one instruction.
// ptxas will not auto-fuse this from C++; must come from PTX fma.rn.f32x2.
__device__ __forceinline__ unsigned long long fma_f32x2(unsigned long long a,
                                                        unsigned long long b,
                                                        unsigned long long c) {
    unsigned long long d;
    asm("fma.rn.f32x2 %0, %1, %2, %3;" : "=l"(d) : "l"(a), "l"(b), "l"(c));
    return d;
}

__device__ __forceinline__ void unpack_f32x2(unsigned long long v, float& lo, float& hi) {
    asm("mov.b64 {%0, %1}, %2;" : "=f"(lo), "=f"(hi) : "l"(v));
}

// Each active thread owns a fixed float4 output chunk column (j4 = t % 50) and
// walks batch rows. Weights for its 4 output columns (80 floats) live in
// registers as 40 f32x2 pairs. x row loaded as 5 x LDG.128.
// Stores: threads 0..499 of a block cover 10 consecutive batch rows x 50 chunks
// -> fully coalesced 16B stores over a contiguous 8000B span.
__global__ __launch_bounds__(512)
void fused_gemm_relu_kernel(const float* __restrict__ x,
                            float* __restrict__ out) {
    const int t = threadIdx.x;
    if (t >= 500) return;                 // 500 = 50 chunks * 10 rows
    const int j4 = t % 50;                // output chunk: columns j4*4 .. j4*4+3
    const int r  = t / 50;                // row-within-block 0..9

    // Load this thread's 4 weight rows (80 floats = 20 x 16B), contiguous.
    unsigned long long w[4][10];
    const ulonglong2* wp =
        reinterpret_cast<const ulonglong2*>(g_weff + j4 * 4 * DICT);
#pragma unroll
    for (int q = 0; q < 20; q++) {
        ulonglong2 v = wp[q];
        w[q / 5][(q % 5) * 2 + 0] = v.x;
        w[q / 5][(q % 5) * 2 + 1] = v.y;
    }

    const long long stride = (long long)gridDim.x * 10;
    for (long long b = (long long)blockIdx.x * 10 + r; b < BATCH_N; b += stride) {
        // Load x row: 20 floats = 10 f32x2 pairs, naturally packed.
        unsigned long long xv[10];
        const ulonglong2* xp = reinterpret_cast<const ulonglong2*>(x + b * DICT);
#pragma unroll
        for (int q = 0; q < 5; q++) {
            ulonglong2 v = xp[q];
            xv[2 * q + 0] = v.x;
            xv[2 * q + 1] = v.y;
        }

        float4 o;
        float* op = &o.x;
#pragma unroll
        for (int jj = 0; jj < 4; jj++) {
            unsigned long long acc = 0ULL;   // (0.0f, 0.0f)
#pragma unroll
            for (int d = 0; d < 10; d++) {
                acc = fma_f32x2(xv[d], w[jj][d], acc);
            }
            float lo, hi;
            unpack_f32x2(acc, lo, hi);
            op[jj] = fmaxf(lo + hi, 0.0f);
        }
        reinterpret_cast<float4*>(out)[b * 50 + j4] = o;
    }
}

extern "C" void kernel_launch(void* const* d_in, const int* in_sizes, int n_in,
                              void* d_out, int out_size) {
    const float* x     = (const float*)d_in[0];
    // d_in[1] = W1 (dead), d_in[2] = W2 (dead)
    const float* W3    = (const float*)d_in[3];
    const float* W4    = (const float*)d_in[4];
    const float* gamma = (const float*)d_in[5];
    float* out = (float*)d_out;

    prep_weff_kernel<<<16, 256>>>(W3, W4, gamma);
    fused_gemm_relu_kernel<<<1184, 512>>>(x, out);
}

// round 5
// speedup vs baseline: 2.0360x; 2.0360x over previous
#include <cuda_runtime.h>
#include <cstdint>

// Problem constants
#define NUM_HEADS 10
#define DICT      20
#define NJ        200            // NUM_HEADS * DICT
#define BATCH_N   262144

#define TILE_ROWS 64             // rows of x staged per tile (64*80B = 5KB/buffer)
#define NUM_TILES (BATCH_N / TILE_ROWS)   // 4096 exactly
#define GRID_X    592
#define BLOCK_X   512

// out[b, j] = relu( x[b,:] . (gamma*W3[j,:] + W4[j,:]) )
// (softmax over a size-1 axis == 1 -> attention block is identity on v; W1, W2 dead.)

__device__ float g_weff[NJ * DICT];   // effective weight, row-major [j][d]

__global__ void prep_weff_kernel(const float* __restrict__ W3,
                                 const float* __restrict__ W4,
                                 const float* __restrict__ gamma) {
    int i = blockIdx.x * blockDim.x + threadIdx.x;
    if (i < NJ * DICT) {
        g_weff[i] = gamma[0] * W3[i] + W4[i];
    }
}

// Packed f32x2 FMA (Blackwell): two fp32 FMAs in one instruction.
__device__ __forceinline__ unsigned long long fma_f32x2(unsigned long long a,
                                                        unsigned long long b,
                                                        unsigned long long c) {
    unsigned long long d;
    asm("fma.rn.f32x2 %0, %1, %2, %3;" : "=l"(d) : "l"(a), "l"(b), "l"(c));
    return d;
}

__device__ __forceinline__ void unpack_f32x2(unsigned long long v, float& lo, float& hi) {
    asm("mov.b64 {%0, %1}, %2;" : "=f"(lo), "=f"(hi) : "l"(v));
}

// cp.async helpers (LDGSTS): async GMEM->SMEM, no consumer-side registers.
__device__ __forceinline__ void cp_async16(uint32_t smem_dst, const void* gmem_src) {
    asm volatile("cp.async.cg.shared.global [%0], [%1], 16;"
                 :: "r"(smem_dst), "l"(gmem_src));
}
__device__ __forceinline__ void cp_commit() {
    asm volatile("cp.async.commit_group;" ::: "memory");
}
__device__ __forceinline__ void cp_wait1() {
    asm volatile("cp.async.wait_group 1;" ::: "memory");
}
__device__ __forceinline__ void cp_wait0() {
    asm volatile("cp.async.wait_group 0;" ::: "memory");
}

// Layout: thread t (t<500) owns output chunk j4 = t%50 (columns j4*4..j4*4+3)
// and row-slot r = t/50 (rows r, r+10, ... within each 64-row tile).
// Weights for its 4 columns (80 floats) live in registers as 40 f32x2 pairs.
// x tiles are double-buffered in smem via cp.async; compute reads are LDS.128
// broadcasts (all lanes of a warp read the same row).
__global__ __launch_bounds__(BLOCK_X)
void fused_gemm_relu_kernel(const float* __restrict__ x,
                            float* __restrict__ out) {
    __shared__ float sx[2][TILE_ROWS * DICT];

    const int t  = threadIdx.x;
    const int j4 = t % 50;
    const int r  = t / 50;
    const bool active = (t < 500);

    // Per-tile load role: 64 rows * 5 float4 = 320 copies; threads 0..319 do one each.
    const int ld_row = t / 5;          // 0..63 (valid when t < 320)
    const int ld_q   = t % 5;          // 0..4
    const bool loader = (t < 320);
    const uint32_t smem_off = (uint32_t)(ld_row * DICT + ld_q * 4) * 4u;
    uint32_t sbase[2];
    sbase[0] = (uint32_t)__cvta_generic_to_shared(&sx[0][0]);
    sbase[1] = (uint32_t)__cvta_generic_to_shared(&sx[1][0]);

    // Load this thread's 4 weight rows (80 floats) into registers.
    unsigned long long w[4][10];
    if (active) {
        const ulonglong2* wp =
            reinterpret_cast<const ulonglong2*>(g_weff + j4 * 4 * DICT);
#pragma unroll
        for (int q = 0; q < 20; q++) {
            ulonglong2 v = wp[q];
            w[q / 5][(q % 5) * 2 + 0] = v.x;
            w[q / 5][(q % 5) * 2 + 1] = v.y;
        }
    }

    int tile = blockIdx.x;
    // Prologue: stage first tile into buffer 0.
    if (tile < NUM_TILES) {
        if (loader) {
            const float* src = x + ((long long)tile * TILE_ROWS + ld_row) * DICT + ld_q * 4;
            cp_async16(sbase[0] + smem_off, src);
        }
    }
    cp_commit();

    int buf = 0;
    for (; tile < NUM_TILES; tile += GRID_X) {
        const int next = tile + GRID_X;
        if (next < NUM_TILES) {
            if (loader) {
                const float* src = x + ((long long)next * TILE_ROWS + ld_row) * DICT + ld_q * 4;
                cp_async16(sbase[buf ^ 1] + smem_off, src);
            }
            cp_commit();
            cp_wait1();            // current buf's load (older group) complete
        } else {
            cp_commit();           // keep group counts consistent across threads
            cp_wait0();
        }
        __syncthreads();

        if (active) {
            const float* xs = sx[buf];
#pragma unroll 2
            for (int idx = r; idx < TILE_ROWS; idx += 10) {
                // Row from smem: 5 x LDS.128 (warp-broadcast, conflict-free).
                unsigned long long xv[10];
                const ulonglong2* xp =
                    reinterpret_cast<const ulonglong2*>(xs + idx * DICT);
#pragma unroll
                for (int q = 0; q < 5; q++) {
                    ulonglong2 v = xp[q];
                    xv[2 * q + 0] = v.x;
                    xv[2 * q + 1] = v.y;
                }

                float4 o;
                float* op = &o.x;
#pragma unroll
                for (int jj = 0; jj < 4; jj++) {
                    unsigned long long acc = 0ULL;   // (0.0f, 0.0f)
#pragma unroll
                    for (int d = 0; d < 10; d++) {
                        acc = fma_f32x2(xv[d], w[jj][d], acc);
                    }
                    float lo, hi;
                    unpack_f32x2(acc, lo, hi);
                    op[jj] = fmaxf(lo + hi, 0.0f);
                }
                const long long row = (long long)tile * TILE_ROWS + idx;
                reinterpret_cast<float4*>(out)[row * 50 + j4] = o;
            }
        }
        __syncthreads();   // all compute on 'buf' done before it is refilled next iter
        buf ^= 1;
    }
}

extern "C" void kernel_launch(void* const* d_in, const int* in_sizes, int n_in,
                              void* d_out, int out_size) {
    const float* x     = (const float*)d_in[0];
    // d_in[1] = W1 (dead), d_in[2] = W2 (dead)
    const float* W3    = (const float*)d_in[3];
    const float* W4    = (const float*)d_in[4];
    const float* gamma = (const float*)d_in[5];
    float* out = (float*)d_out;

    prep_weff_kernel<<<16, 256>>>(W3, W4, gamma);
    fused_gemm_relu_kernel<<<GRID_X, BLOCK_X>>>(x, out);
}